// round 8
// baseline (speedup 1.0000x reference)
#include <cuda_runtime.h>

#define BSZ 256
#define HSZ 512
#define NSZ 16
#define TSTEPS 63
#define ODIM 9
#define NBLK 128
#define NTHR 512

typedef unsigned long long ull;

// ---------- packed f32x2 helpers ----------
__device__ __forceinline__ ull pack2(float lo, float hi) {
    ull r; asm("mov.b64 %0,{%1,%2};" : "=l"(r) : "f"(lo), "f"(hi)); return r;
}
__device__ __forceinline__ float2 unpack2(ull v) {
    float2 r; asm("mov.b64 {%0,%1},%2;" : "=f"(r.x), "=f"(r.y) : "l"(v)); return r;
}
__device__ __forceinline__ ull fma2v(ull a, ull b, ull c) {
    ull d; asm("fma.rn.f32x2 %0,%1,%2,%3;" : "=l"(d) : "l"(a), "l"(b), "l"(c)); return d;
}
__device__ __forceinline__ float gelu_exact(float x) {
    return 0.5f * x * (1.0f + erff(x * 0.70710678118654752440f));
}
__device__ __forceinline__ float sigm(float x) {
    return 1.0f / (1.0f + expf(-x));
}

// ---------- scratch ----------
__device__ __align__(16) float g_enc[BSZ * 6 * HSZ];
__device__ __align__(16) float g_states[2 * BSZ * HSZ * NSZ];
__device__ __align__(16) float g_gact[BSZ * HSZ];
__device__ __align__(16) float g_dp[BSZ * HSZ];
__device__ __align__(16) float g_ctx[BSZ * HSZ];
__device__ __align__(16) float g_z0[BSZ * HSZ];
__device__ __align__(16) float g_z1[BSZ * HSZ];
__device__ __align__(16) float g_dec[BSZ * 4];
__device__ float g_ps0[16 * BSZ], g_pq0[16 * BSZ];
__device__ float g_ps1[16 * BSZ], g_pq1[16 * BSZ];
__device__ int g_count, g_epoch;

// smem layout (floats): Ws0[512*36] | Ws1[512*36] | Aregion[512*33]
#define WS_STRIDE 36
#define AS_STRIDE 33
#define SMEM_W (512 * WS_STRIDE)
#define SMEM_DYN_BYTES ((2 * SMEM_W + 512 * AS_STRIDE) * 4)

// ============================================================
// setup kernels
// ============================================================
__global__ void k_enc(const float* __restrict__ inseq,
                      const float* __restrict__ inW,
                      const float* __restrict__ inb) {
    int idx = blockIdx.x * 256 + threadIdx.x;
    int h = idx & (HSZ - 1);
    int bs = idx >> 9;
    int b = bs / 6, s = bs - b * 6;
    const float* r = inseq + (b * 64 + s) * 3;
    g_enc[idx] = fmaf(r[0], inW[h],
                 fmaf(r[1], inW[HSZ + h],
                 fmaf(r[2], inW[2 * HSZ + h], inb[h])));
}

__global__ void k_init() {
    int idx = blockIdx.x * 256 + threadIdx.x;
    if (idx < 2 * BSZ * HSZ * NSZ) g_states[idx] = 0.0f;
    if (idx < BSZ * HSZ) g_ctx[idx] = 0.0f;
    if (idx == 0) { g_count = 0; g_epoch = 0; }
}

__global__ void __launch_bounds__(256)
k_first(const float* __restrict__ inW, const float* __restrict__ inb,
        const float* __restrict__ A0, const float* __restrict__ B0,
        const float* __restrict__ C0, const float* __restrict__ D0) {
    int idx = blockIdx.x * 256 + threadIdx.x;
    int h = idx & (HSZ - 1);
    int b = idx >> 9;
    float x = inW[2 * HSZ + h] + inb[h];
    g_dp[idx] = x;
    const float4* B4 = (const float4*)(B0 + h * NSZ);
    const float4* C4 = (const float4*)(C0 + h * NSZ);
    float4* S4p = (float4*)(g_states + ((size_t)b * HSZ + h) * NSZ);
    float acc = 0.0f;
#pragma unroll
    for (int q = 0; q < 4; q++) {
        float4 bm = B4[q], c = C4[q];
        float4 s = make_float4(bm.x * x, bm.y * x, bm.z * x, bm.w * x);
        acc += c.x * s.x + c.y * s.y + c.z * s.z + c.w * s.w;
        S4p[q] = s;
    }
    g_gact[idx] = gelu_exact(fmaf(D0[h], x, acc));
}

// ============================================================
// global software barrier (all NBLK blocks co-resident)
// ============================================================
__device__ __forceinline__ void gbar(int& ep) {
    __syncthreads();
    if (threadIdx.x == 0) {
        ep++;
        __threadfence();
        if (atomicAdd(&g_count, 1) == NBLK - 1) {
            atomicExch(&g_count, 0);
            __threadfence();
            atomicExch(&g_epoch, ep);
        } else {
            while (*(volatile int*)&g_epoch < ep) __nanosleep(64);
        }
        __threadfence();
    }
    __syncthreads();
}

// ============================================================
// GEMM phase: block tile 32x32, in-block split-K-8, f32x2
// ============================================================
__device__ __forceinline__ void gemm_phase(
    int isstep0, const float* __restrict__ Wsm, float* __restrict__ Aregion,
    float* __restrict__ zbuf, float* __restrict__ ps, float* __restrict__ pq,
    const float* __restrict__ obias) {
    int t = threadIdx.x, bid = blockIdx.x;
    int r0 = (bid >> 4) * 32, c0 = (bid & 15) * 32;

    // stage A (gact rows r0..r0+32, all K) transposed into Aregion[k][33]
    {
        int row = t & 31, kb = t >> 5;          // kb 0..15
        const float4* src = (const float4*)(g_gact + (r0 + row) * HSZ + kb * 32);
#pragma unroll
        for (int i = 0; i < 8; i++) {
            float4 v = __ldcg(src + i);
            int k = kb * 32 + i * 4;
            Aregion[(k + 0) * AS_STRIDE + row] = v.x;
            Aregion[(k + 1) * AS_STRIDE + row] = v.y;
            Aregion[(k + 2) * AS_STRIDE + row] = v.z;
            Aregion[(k + 3) * AS_STRIDE + row] = v.w;
        }
    }
    __syncthreads();

    int ks = t >> 6;                  // k-slice 0..7 (64 k each)
    int pos = t & 63;
    int cq = pos & 7, rg = pos >> 3;  // col-quad, row-group
    int rbase = rg * 4, cbase = cq * 4;

    ull acc[4][2];
#pragma unroll
    for (int i = 0; i < 4; i++) { acc[i][0] = 0ULL; acc[i][1] = 0ULL; }

    int kbeg = ks * 64;
#pragma unroll 4
    for (int kk = 0; kk < 64; kk++) {
        int k = kbeg + kk;
        ulonglong2 b = *(const ulonglong2*)&Wsm[k * WS_STRIDE + cbase];
        float a0 = Aregion[k * AS_STRIDE + rbase + 0];
        float a1 = Aregion[k * AS_STRIDE + rbase + 1];
        float a2 = Aregion[k * AS_STRIDE + rbase + 2];
        float a3 = Aregion[k * AS_STRIDE + rbase + 3];
        ull d0 = pack2(a0, a0), d1 = pack2(a1, a1);
        ull d2 = pack2(a2, a2), d3 = pack2(a3, a3);
        acc[0][0] = fma2v(d0, b.x, acc[0][0]); acc[0][1] = fma2v(d0, b.y, acc[0][1]);
        acc[1][0] = fma2v(d1, b.x, acc[1][0]); acc[1][1] = fma2v(d1, b.y, acc[1][1]);
        acc[2][0] = fma2v(d2, b.x, acc[2][0]); acc[2][1] = fma2v(d2, b.y, acc[2][1]);
        acc[3][0] = fma2v(d3, b.x, acc[3][0]); acc[3][1] = fma2v(d3, b.y, acc[3][1]);
    }
    __syncthreads();   // A no longer needed; reuse region for partials

    // write partials: ured[(ks*64 + pos)*8 + (i*2 + jp)]
    ull* ured = (ull*)Aregion;
#pragma unroll
    for (int i = 0; i < 4; i++) {
        ured[((size_t)(ks * 64 + pos)) * 8 + i * 2 + 0] = acc[i][0];
        ured[((size_t)(ks * 64 + pos)) * 8 + i * 2 + 1] = acc[i][1];
    }
    __syncthreads();

    // reduce: thread t -> row rloc = t>>4, colpair cp2 = t&15 (cols 2cp2, 2cp2+1)
    {
        int rloc = t >> 4, cp2 = t & 15;
        int prg = rloc >> 2, pi = rloc & 3;
        int pcq = cp2 >> 1, pjp = cp2 & 1;
        int ppos = prg * 8 + pcq;
        int o = pi * 2 + pjp;
        float zx = 0.0f, zy = 0.0f;
#pragma unroll
        for (int s = 0; s < 8; s++) {
            float2 v = unpack2(ured[((size_t)(s * 64 + ppos)) * 8 + o]);
            zx += v.x; zy += v.y;
        }
        int row = r0 + rloc, col = c0 + cp2 * 2;
        zx += obias[col]; zy += obias[col + 1];
        float z0, z1;
        if (isstep0) {
            z0 = zx + __ldg(&g_dp[row * HSZ + col]);
            z1 = zy + __ldg(&g_dp[row * HSZ + col + 1]);
        } else { z0 = 2.0f * zx; z1 = 2.0f * zy; }
        zbuf[row * HSZ + col] = z0;
        zbuf[row * HSZ + col + 1] = z1;

        float s = z0 + z1, q = z0 * z0 + z1 * z1;
        int lane = t & 31;
#pragma unroll
        for (int d = 1; d < 16; d <<= 1) {
            s += __shfl_xor_sync(0xFFFFFFFFu, s, d);
            q += __shfl_xor_sync(0xFFFFFFFFu, q, d);
        }
        if ((lane & 15) == 0) {
            ps[(bid & 15) * BSZ + row] = s;
            pq[(bid & 15) * BSZ + row] = q;
        }
    }
}

// ============================================================
// persistent decode kernel
// ============================================================
__global__ void __launch_bounds__(NTHR, 1)
k_persist(const float* __restrict__ inW, const float* __restrict__ inb,
          const float* __restrict__ A, const float* __restrict__ Bm,
          const float* __restrict__ Cm, const float* __restrict__ D,
          const float* __restrict__ oW, const float* __restrict__ ob,
          const float* __restrict__ lng, const float* __restrict__ lnb,
          const float* __restrict__ hW, const float* __restrict__ hb,
          float* __restrict__ out) {
    extern __shared__ float smf[];
    float* Ws0 = smf;
    float* Ws1 = smf + SMEM_W;
    float* Aregion = smf + 2 * SMEM_W;

    __shared__ float s_mu[8], s_rs[8];
    __shared__ float s_gv[2][12];
    __shared__ float s_dv[2][3];
    __shared__ int s_ptr[2];

    int t = threadIdx.x, bid = blockIdx.x;
    int lane = t & 31, w = t >> 5;

    const float* A1 = A + HSZ * NSZ; const float* B1 = Bm + HSZ * NSZ;
    const float* C1 = Cm + HSZ * NSZ; const float* D1 = D + HSZ;
    const float* lng1 = lng + HSZ; const float* lnb1 = lnb + HSZ;

    // ---- stage W (both layers) once: this block's 32-col slice ----
    {
        int c0 = (bid & 15) * 32;
        const float4* w0 = (const float4*)(oW + (size_t)t * HSZ + c0);
        const float4* w1 = (const float4*)(oW + (size_t)HSZ * HSZ + (size_t)t * HSZ + c0);
        float* d0 = Ws0 + t * WS_STRIDE;
        float* d1 = Ws1 + t * WS_STRIDE;
#pragma unroll
        for (int i = 0; i < 8; i++) {
            *(float4*)(d0 + i * 4) = __ldg(w0 + i);
            *(float4*)(d1 + i * 4) = __ldg(w1 + i);
        }
    }
    __syncthreads();

    // S-phase decomposition
    int rg8 = bid >> 2;             // row-group (8 rows)
    int hwin = (bid & 3) * 128;     // h window
    int rows0 = rg8 * 8;
    int hl = t >> 2, nq = t & 3;
    int h = hwin + hl;

    int ep = 0;
    for (int i = 0; i < TSTEPS; i++) {
        int s0f = (i == 0) ? 1 : 0;

        // ---------- G0 ----------
        gemm_phase(s0f, Ws0, Aregion, g_z0, g_ps0, g_pq0, ob);
        gbar(ep);

        // ---------- S1: LN0 + layer-1 SSM ----------
        {
            // row stats (warps 0..7, one row each)
            if (w < 8) {
                int row = rows0 + w;
                float s = (lane < 16) ? __ldcg(&g_ps0[lane * BSZ + row]) : 0.0f;
                float q = (lane < 16) ? __ldcg(&g_pq0[lane * BSZ + row]) : 0.0f;
#pragma unroll
                for (int d = 1; d < 32; d <<= 1) {
                    s += __shfl_xor_sync(0xFFFFFFFFu, s, d);
                    q += __shfl_xor_sync(0xFFFFFFFFu, q, d);
                }
                if (lane == 0) {
                    float m = s * (1.0f / HSZ);
                    s_mu[w] = m;
                    s_rs[w] = rsqrtf(q * (1.0f / HSZ) - m * m + 1e-5f);
                }
            }
            __syncthreads();
            // x tile: 8 rows x 128 h
            float* xs = Aregion;
#pragma unroll
            for (int rep = 0; rep < 2; rep++) {
                int idx = t + rep * NTHR;
                int r = idx >> 7, hloc = idx & 127;
                int hh = hwin + hloc;
                float z = __ldcg(&g_z0[(rows0 + r) * HSZ + hh]);
                xs[idx] = (z - s_mu[r]) * s_rs[r] * __ldg(&lng[hh]) + __ldg(&lnb[hh]);
            }
            __syncthreads();
            // SSM layer 1
            float4 ca = __ldg((const float4*)(A1 + h * NSZ + nq * 4));
            float4 cb = __ldg((const float4*)(B1 + h * NSZ + nq * 4));
            float4 cc = __ldg((const float4*)(C1 + h * NSZ + nq * 4));
            float dd = __ldg(&D1[h]);
#pragma unroll
            for (int r = 0; r < 8; r++) {
                int row = rows0 + r;
                float4* sp = (float4*)(g_states + ((size_t)BSZ * HSZ + (size_t)row * HSZ + h) * NSZ + nq * 4);
                float4 s = *sp;
                float x = xs[r * 128 + hl];
                s.x = fmaf(ca.x, s.x, cb.x * x); s.y = fmaf(ca.y, s.y, cb.y * x);
                s.z = fmaf(ca.z, s.z, cb.z * x); s.w = fmaf(ca.w, s.w, cb.w * x);
                *sp = s;
                float cd = cc.x * s.x + cc.y * s.y + cc.z * s.z + cc.w * s.w;
                cd += __shfl_xor_sync(0xFFFFFFFFu, cd, 1);
                cd += __shfl_xor_sync(0xFFFFFFFFu, cd, 2);
                if (nq == 0)
                    g_gact[row * HSZ + h] = gelu_exact(fmaf(dd, x, cd));
            }
        }
        gbar(ep);

        // ---------- G1 ----------
        gemm_phase(s0f, Ws1, Aregion, g_z1, g_ps1, g_pq1, ob + HSZ);
        gbar(ep);

        // ---------- HEAD (2 rows per block) ----------
        {
            int r0h = bid * 2;
            // stats (warps 0,1 -> rows)
            if (w < 2) {
                int row = r0h + w;
                float s = (lane < 16) ? __ldcg(&g_ps1[lane * BSZ + row]) : 0.0f;
                float q = (lane < 16) ? __ldcg(&g_pq1[lane * BSZ + row]) : 0.0f;
#pragma unroll
                for (int d = 1; d < 32; d <<= 1) {
                    s += __shfl_xor_sync(0xFFFFFFFFu, s, d);
                    q += __shfl_xor_sync(0xFFFFFFFFu, q, d);
                }
                if (lane == 0) {
                    float m = s * (1.0f / HSZ);
                    s_mu[w] = m;
                    s_rs[w] = rsqrtf(q * (1.0f / HSZ) - m * m + 1e-5f);
                }
            }
            __syncthreads();
            float* xd2 = Aregion;       // [2][512]
            float g = __ldg(&lng1[t]), bb = __ldg(&lnb1[t]);
            float za = __ldcg(&g_z1[r0h * HSZ + t]);
            float zb = __ldcg(&g_z1[(r0h + 1) * HSZ + t]);
            float ctx0 = g_ctx[r0h * HSZ + t];
            float ctx1 = g_ctx[(r0h + 1) * HSZ + t];
            xd2[t] = (za - s_mu[0]) * s_rs[0] * g + bb + ctx0;
            xd2[NTHR + t] = (zb - s_mu[1]) * s_rs[1] * g + bb + ctx1;
            __syncthreads();
            if (w < ODIM) {
                float a0 = 0.0f, a1 = 0.0f;
#pragma unroll
                for (int q = 0; q < 16; q++) {
                    int k = q * 32 + lane;
                    float wk = __ldg(&hW[k * ODIM + w]);
                    a0 = fmaf(xd2[k], wk, a0);
                    a1 = fmaf(xd2[NTHR + k], wk, a1);
                }
#pragma unroll
                for (int d = 16; d; d >>= 1) {
                    a0 += __shfl_xor_sync(0xFFFFFFFFu, a0, d);
                    a1 += __shfl_xor_sync(0xFFFFFFFFu, a1, d);
                }
                if (lane == 0) {
                    s_gv[0][w] = a0 + __ldg(&hb[w]);
                    s_gv[1][w] = a1 + __ldg(&hb[w]);
                }
            }
            __syncthreads();
            bool is_out = ((i & 1) == 0);
            if (is_out) {
                if (t < ODIM) out[r0h * (TSTEPS * ODIM) + i * ODIM + t] = sigm(s_gv[0][t]);
                if (t >= 32 && t < 32 + ODIM)
                    out[(r0h + 1) * (TSTEPS * ODIM) + i * ODIM + (t - 32)] = sigm(s_gv[1][t - 32]);
                if (t < 2) {
                    s_dv[t][0] = (sigm(s_gv[t][0]) > 0.5f) ? 1.0f : 0.0f;
                    s_dv[t][1] = 1.0f; s_dv[t][2] = 0.0f;
                }
            } else {
                if (t < 2) {
                    float best = sigm(s_gv[t][3]); int p = 0;
#pragma unroll
                    for (int c = 1; c < 6; c++) {
                        float v = sigm(s_gv[t][3 + c]);
                        if (v > best) { best = v; p = c; }
                    }
                    s_ptr[t] = p;
                    s_dv[t][0] = 0.0f; s_dv[t][1] = 0.0f; s_dv[t][2] = 1.0f;
                }
                __syncthreads();
                const float* ev0 = g_enc + (r0h * 6 + s_ptr[0]) * HSZ;
                const float* ev1 = g_enc + ((r0h + 1) * 6 + s_ptr[1]) * HSZ;
                g_ctx[r0h * HSZ + t] = ctx0 + ev0[t];
                g_ctx[(r0h + 1) * HSZ + t] = ctx1 + ev1[t];
                if (w < ODIM) {
                    float a0 = 0.0f, a1 = 0.0f;
#pragma unroll
                    for (int q = 0; q < 16; q++) {
                        int k = q * 32 + lane;
                        float wk = __ldg(&hW[k * ODIM + w]);
                        a0 = fmaf(ev0[k], wk, a0);
                        a1 = fmaf(ev1[k], wk, a1);
                    }
#pragma unroll
                    for (int d = 16; d; d >>= 1) {
                        a0 += __shfl_xor_sync(0xFFFFFFFFu, a0, d);
                        a1 += __shfl_xor_sync(0xFFFFFFFFu, a1, d);
                    }
                    if (lane == 0) {
                        out[r0h * (TSTEPS * ODIM) + i * ODIM + w] = sigm(s_gv[0][w] + a0);
                        out[(r0h + 1) * (TSTEPS * ODIM) + i * ODIM + w] = sigm(s_gv[1][w] + a1);
                    }
                }
            }
            __syncthreads();
            if (t < 2) {
                g_dec[(r0h + t) * 4 + 0] = s_dv[t][0];
                g_dec[(r0h + t) * 4 + 1] = s_dv[t][1];
                g_dec[(r0h + t) * 4 + 2] = s_dv[t][2];
            }
        }
        if (i == TSTEPS - 1) break;
        gbar(ep);

        // ---------- S0: decoder proj + layer-0 SSM ----------
        {
            float w0 = __ldg(&inW[h]), w1 = __ldg(&inW[HSZ + h]);
            float w2 = __ldg(&inW[2 * HSZ + h]), ib = __ldg(&inb[h]);
            float4 ca = __ldg((const float4*)(A + h * NSZ + nq * 4));
            float4 cb = __ldg((const float4*)(Bm + h * NSZ + nq * 4));
            float4 cc = __ldg((const float4*)(Cm + h * NSZ + nq * 4));
            float dd = __ldg(&D[h]);
#pragma unroll
            for (int r = 0; r < 8; r++) {
                int row = rows0 + r;
                float d0 = __ldcg(&g_dec[row * 4 + 0]);
                float d1 = __ldcg(&g_dec[row * 4 + 1]);
                float d2 = __ldcg(&g_dec[row * 4 + 2]);
                float x = fmaf(d0, w0, fmaf(d1, w1, fmaf(d2, w2, ib)));
                float4* sp = (float4*)(g_states + ((size_t)row * HSZ + h) * NSZ + nq * 4);
                float4 s = *sp;
                s.x = fmaf(ca.x, s.x, cb.x * x); s.y = fmaf(ca.y, s.y, cb.y * x);
                s.z = fmaf(ca.z, s.z, cb.z * x); s.w = fmaf(ca.w, s.w, cb.w * x);
                *sp = s;
                float cd = cc.x * s.x + cc.y * s.y + cc.z * s.z + cc.w * s.w;
                cd += __shfl_xor_sync(0xFFFFFFFFu, cd, 1);
                cd += __shfl_xor_sync(0xFFFFFFFFu, cd, 2);
                if (nq == 0)
                    g_gact[row * HSZ + h] = gelu_exact(fmaf(dd, x, cd));
            }
        }
        gbar(ep);
    }
}

// ============================================================
// Launch: 4 graph nodes
// ============================================================
extern "C" void kernel_launch(void* const* d_in, const int* in_sizes, int n_in,
                              void* d_out, int out_size) {
    int o = (n_in >= 14) ? 1 : 0;
    const float* inseq = (const float*)d_in[0];
    const float* inW = (const float*)d_in[1 + o];
    const float* inb = (const float*)d_in[2 + o];
    const float* A   = (const float*)d_in[3 + o];
    const float* Bm  = (const float*)d_in[4 + o];
    const float* Cm  = (const float*)d_in[5 + o];
    const float* D   = (const float*)d_in[6 + o];
    const float* oW  = (const float*)d_in[7 + o];
    const float* ob  = (const float*)d_in[8 + o];
    const float* lng = (const float*)d_in[9 + o];
    const float* lnb = (const float*)d_in[10 + o];
    const float* hW  = (const float*)d_in[11 + o];
    const float* hb  = (const float*)d_in[12 + o];
    float* out = (float*)d_out;

    cudaFuncSetAttribute(k_persist, cudaFuncAttributeMaxDynamicSharedMemorySize,
                         SMEM_DYN_BYTES);

    k_enc<<<(BSZ * 6 * HSZ) / 256, 256>>>(inseq, inW, inb);
    k_init<<<(2 * BSZ * HSZ * NSZ) / 256, 256>>>();
    k_first<<<(BSZ * HSZ) / 256, 256>>>(inW, inb, A, Bm, Cm, D);
    k_persist<<<NBLK, NTHR, SMEM_DYN_BYTES>>>(inW, inb, A, Bm, Cm, D,
                                              oW, ob, lng, lnb, hW, hb, out);
}

// round 10
// speedup vs baseline: 1.1062x; 1.1062x over previous
#include <cuda_runtime.h>

#define BSZ 256
#define HSZ 512
#define NSZ 16
#define TSTEPS 63
#define ODIM 9
#define NBLK 128
#define NTHR 1024

typedef unsigned long long ull;

__device__ __forceinline__ ull pack2(float lo, float hi) {
    ull r; asm("mov.b64 %0,{%1,%2};" : "=l"(r) : "f"(lo), "f"(hi)); return r;
}
__device__ __forceinline__ float2 unpack2(ull v) {
    float2 r; asm("mov.b64 {%0,%1},%2;" : "=f"(r.x), "=f"(r.y) : "l"(v)); return r;
}
__device__ __forceinline__ ull fma2v(ull a, ull b, ull c) {
    ull d; asm("fma.rn.f32x2 %0,%1,%2,%3;" : "=l"(d) : "l"(a), "l"(b), "l"(c)); return d;
}
__device__ __forceinline__ float gelu_exact(float x) {
    return 0.5f * x * (1.0f + erff(x * 0.70710678118654752440f));
}
__device__ __forceinline__ float sigm(float x) {
    return 1.0f / (1.0f + expf(-x));
}

// ---------- global scratch ----------
__device__ __align__(16) float g_enc[BSZ * 6 * HSZ];
__device__ __align__(16) float g_gact[BSZ * HSZ];
__device__ __align__(16) float g_part[8 * BSZ * HSZ];   // split-K partials (8 chunks)
__device__ int g_count, g_epoch;

// dynamic smem: Ws[2][64][256] | As[64][36]
#define WSL (64 * 256)
#define AS_OFF (2 * WSL)
#define SMEM_FLOATS (2 * WSL + 64 * 36)
#define SMEM_BYTES (SMEM_FLOATS * 4)

// ============================================================
__global__ void k_enc(const float* __restrict__ inseq,
                      const float* __restrict__ inW,
                      const float* __restrict__ inb) {
    int idx = blockIdx.x * 256 + threadIdx.x;   // < B*6*H
    int h = idx & (HSZ - 1);
    int bs = idx >> 9;
    int b = bs / 6, s = bs - b * 6;
    const float* r = inseq + (b * 64 + s) * 3;
    g_enc[idx] = fmaf(r[0], inW[h],
                 fmaf(r[1], inW[HSZ + h],
                 fmaf(r[2], inW[2 * HSZ + h], inb[h])));
}

__global__ void k_init() {
    if (threadIdx.x == 0) { g_count = 0; g_epoch = 0; }
}

// ============================================================
// global software barrier (all NBLK blocks co-resident)
// ============================================================
__device__ __forceinline__ void gbar(int& ep) {
    __syncthreads();
    if (threadIdx.x == 0) {
        ep++;
        __threadfence();
        if (atomicAdd(&g_count, 1) == NBLK - 1) {
            atomicExch(&g_count, 0);
            __threadfence();
            atomicExch(&g_epoch, ep);
        } else {
            while (*(volatile int*)&g_epoch < ep) { }
        }
        __threadfence();
    }
    __syncthreads();
}

// ============================================================
// GEMM phase: tile 32r x 256c x 64k, partials to g_part[kc]
// ============================================================
__device__ __forceinline__ void g_phase(const float* __restrict__ Wk,
                                        float* __restrict__ As,
                                        int rt, int ct, int kc) {
    int t = threadIdx.x;
    if (t < 512) {
        int row = t & 31, kb = t >> 5;      // kb 0..15
        float4 v = __ldcg((const float4*)&g_gact[(rt * 32 + row) * HSZ + kc * 64 + kb * 4]);
        As[(kb * 4 + 0) * 36 + row] = v.x;
        As[(kb * 4 + 1) * 36 + row] = v.y;
        As[(kb * 4 + 2) * 36 + row] = v.z;
        As[(kb * 4 + 3) * 36 + row] = v.w;
    }
    __syncthreads();

    int ww = t >> 5, lane = t & 31;
    int lr = lane >> 2, lc = lane & 3;
    int cb = ww * 8 + lc * 2;               // local col 0..255 (even)

    ull a00 = 0, a01 = 0, a10 = 0, a11 = 0;
#pragma unroll 16
    for (int k = 0; k < 64; k++) {
        ulonglong2 u = *(const ulonglong2*)&As[k * 36 + lr * 4];  // 4 rows = 2 pairs
        float2 bf = *(const float2*)&Wk[k * 256 + cb];            // 2 cols
        ull b0 = pack2(bf.x, bf.x), b1 = pack2(bf.y, bf.y);
        a00 = fma2v(u.x, b0, a00); a01 = fma2v(u.x, b1, a01);
        a10 = fma2v(u.y, b0, a10); a11 = fma2v(u.y, b1, a11);
    }

    int r0 = rt * 32 + lr * 4, c = ct * 256 + cb;
    float2 p0 = unpack2(a00), q0 = unpack2(a01);
    float2 p1 = unpack2(a10), q1 = unpack2(a11);
    float* P = g_part + (size_t)kc * BSZ * HSZ;
    *(float2*)&P[(r0 + 0) * HSZ + c] = make_float2(p0.x, q0.x);
    *(float2*)&P[(r0 + 1) * HSZ + c] = make_float2(p0.y, q0.y);
    *(float2*)&P[(r0 + 2) * HSZ + c] = make_float2(p1.x, q1.x);
    *(float2*)&P[(r0 + 3) * HSZ + c] = make_float2(p1.y, q1.y);
    __syncthreads();
}

// ============================================================
// persistent decode kernel
// ============================================================
__global__ void __launch_bounds__(NTHR, 1)
k_persist(const float* __restrict__ inW, const float* __restrict__ inb,
          const float* __restrict__ A, const float* __restrict__ Bm,
          const float* __restrict__ Cm, const float* __restrict__ D,
          const float* __restrict__ oW, const float* __restrict__ ob,
          const float* __restrict__ lng, const float* __restrict__ lnb,
          const float* __restrict__ hW, const float* __restrict__ hb,
          float* __restrict__ out) {
    extern __shared__ float smf[];
    float* Ws = smf;                 // [2][64][256]
    float* As = smf + AS_OFF;        // [64][36] (also reused as xdc[2][512])

    __shared__ float red_s[32], redq_s[32];
    __shared__ float stat_s[4];      // mu0, rs0, mu1, rs1
    __shared__ float s_gv[2][12];
    __shared__ float s_dv[2][3];
    __shared__ int s_ptr[2];

    int t = threadIdx.x, bid = blockIdx.x;
    int lane = t & 31, ww = t >> 5;
    int bb = t >> 9, h = t & 511;
    int b = bid * 2 + bb;
    // GEMM tile assignment
    int rt = bid & 7, ct = (bid >> 3) & 1, kc = bid >> 4;

    const float* A1p = A + HSZ * NSZ;  const float* B1p = Bm + HSZ * NSZ;
    const float* C1p = Cm + HSZ * NSZ; const float* D1p = D + HSZ;
    const float* lng1 = lng + HSZ;     const float* lnb1 = lnb + HSZ;
    const float* ob1 = ob + HSZ;

    // ---- stage W slice (both layers) once ----
    {
        const size_t HH = (size_t)HSZ * HSZ;
#pragma unroll
        for (int i = 0; i < 8; i++) {
            int fidx = t + i * NTHR;           // 0..8191 float4s
            int l = fidx >> 12, rem = fidx & 4095;
            int k = rem >> 6, c4 = rem & 63;
            float4 v = __ldg((const float4*)&oW[l * HH + (size_t)(kc * 64 + k) * HSZ + ct * 256 + c4 * 4]);
            *(float4*)&Ws[(l * 64 + k) * 256 + c4 * 4] = v;
        }
    }

    // ---- per-thread registers: states + ctx ----
    float s0[NSZ], s1[NSZ];
    float ctx = 0.0f;

    // ---- initial S0: dec=[0,0,1], states zero ----
    {
        float x = __ldg(&inW[2 * HSZ + h]) + __ldg(&inb[h]);
        float acc = 0.0f;
#pragma unroll
        for (int q = 0; q < 4; q++) {
            float4 cb4 = __ldg((const float4*)(Bm + h * NSZ + q * 4));
            float4 cc4 = __ldg((const float4*)(Cm + h * NSZ + q * 4));
            s0[q * 4 + 0] = cb4.x * x; s0[q * 4 + 1] = cb4.y * x;
            s0[q * 4 + 2] = cb4.z * x; s0[q * 4 + 3] = cb4.w * x;
            acc += cc4.x * s0[q * 4] + cc4.y * s0[q * 4 + 1]
                 + cc4.z * s0[q * 4 + 2] + cc4.w * s0[q * 4 + 3];
        }
#pragma unroll
        for (int n = 0; n < NSZ; n++) s1[n] = 0.0f;
        g_gact[b * HSZ + h] = gelu_exact(fmaf(__ldg(&D[h]), x, acc));
    }

    int ep = 0;
    gbar(ep);

    for (int i = 0; i < TSTEPS; i++) {
        int s0f = (i == 0) ? 1 : 0;

        // ---------- G0 ----------
        g_phase(Ws, As, rt, ct, kc);
        gbar(ep);

        // ---------- S1: partials -> z0, LN, layer-1 SSM -> gact ----------
        {
            float y = 0.0f;
#pragma unroll
            for (int z = 0; z < 8; z++) y += __ldcg(&g_part[((size_t)z * BSZ + b) * HSZ + h]);
            y += __ldg(&ob[h]);
            float zz;
            if (s0f) zz = y + (__ldg(&inW[2 * HSZ + h]) + __ldg(&inb[h]));
            else     zz = 2.0f * y;

            float s = zz, q = zz * zz;
#pragma unroll
            for (int d = 16; d; d >>= 1) {
                s += __shfl_xor_sync(0xFFFFFFFFu, s, d);
                q += __shfl_xor_sync(0xFFFFFFFFu, q, d);
            }
            if (lane == 0) { red_s[ww] = s; redq_s[ww] = q; }
            __syncthreads();
            if (t == 0) {
#pragma unroll
                for (int hf = 0; hf < 2; hf++) {
                    float ss = 0.0f, qq = 0.0f;
#pragma unroll
                    for (int k = 0; k < 16; k++) { ss += red_s[hf * 16 + k]; qq += redq_s[hf * 16 + k]; }
                    float m = ss * (1.0f / HSZ);
                    stat_s[hf * 2] = m;
                    stat_s[hf * 2 + 1] = rsqrtf(qq * (1.0f / HSZ) - m * m + 1e-5f);
                }
            }
            __syncthreads();
            float x = (zz - stat_s[bb * 2]) * stat_s[bb * 2 + 1] * __ldg(&lng[h]) + __ldg(&lnb[h]);

            float acc = 0.0f;
#pragma unroll
            for (int q4 = 0; q4 < 4; q4++) {
                float4 ca = __ldg((const float4*)(A1p + h * NSZ + q4 * 4));
                float4 cb4 = __ldg((const float4*)(B1p + h * NSZ + q4 * 4));
                float4 cc4 = __ldg((const float4*)(C1p + h * NSZ + q4 * 4));
                s1[q4 * 4 + 0] = fmaf(ca.x, s1[q4 * 4 + 0], cb4.x * x);
                s1[q4 * 4 + 1] = fmaf(ca.y, s1[q4 * 4 + 1], cb4.y * x);
                s1[q4 * 4 + 2] = fmaf(ca.z, s1[q4 * 4 + 2], cb4.z * x);
                s1[q4 * 4 + 3] = fmaf(ca.w, s1[q4 * 4 + 3], cb4.w * x);
                acc += cc4.x * s1[q4 * 4] + cc4.y * s1[q4 * 4 + 1]
                     + cc4.z * s1[q4 * 4 + 2] + cc4.w * s1[q4 * 4 + 3];
            }
            g_gact[b * HSZ + h] = gelu_exact(fmaf(__ldg(&D1p[h]), x, acc));
        }
        gbar(ep);

        // ---------- G1 ----------
        g_phase(Ws + WSL, As, rt, ct, kc);
        gbar(ep);

        // ---------- HEAD + fused next-step S0 (block-local b-pair) ----------
        {
            float y = 0.0f;
#pragma unroll
            for (int z = 0; z < 8; z++) y += __ldcg(&g_part[((size_t)z * BSZ + b) * HSZ + h]);
            y += __ldg(&ob1[h]);
            float zz;
            if (s0f) zz = y + (__ldg(&inW[2 * HSZ + h]) + __ldg(&inb[h]));
            else     zz = 2.0f * y;

            float s = zz, q = zz * zz;
#pragma unroll
            for (int d = 16; d; d >>= 1) {
                s += __shfl_xor_sync(0xFFFFFFFFu, s, d);
                q += __shfl_xor_sync(0xFFFFFFFFu, q, d);
            }
            if (lane == 0) { red_s[ww] = s; redq_s[ww] = q; }
            __syncthreads();
            if (t == 0) {
#pragma unroll
                for (int hf = 0; hf < 2; hf++) {
                    float ss = 0.0f, qq = 0.0f;
#pragma unroll
                    for (int k = 0; k < 16; k++) { ss += red_s[hf * 16 + k]; qq += redq_s[hf * 16 + k]; }
                    float m = ss * (1.0f / HSZ);
                    stat_s[hf * 2] = m;
                    stat_s[hf * 2 + 1] = rsqrtf(qq * (1.0f / HSZ) - m * m + 1e-5f);
                }
            }
            __syncthreads();
            float xd = (zz - stat_s[bb * 2]) * stat_s[bb * 2 + 1] * __ldg(&lng1[h]) + __ldg(&lnb1[h]);
            float* xdc = As;              // reuse [2][512]
            xdc[bb * 512 + h] = xd + ctx;
            __syncthreads();

            int half = ww >> 4, wl = ww & 15;
            if (wl < ODIM) {
                float a = 0.0f;
#pragma unroll
                for (int qq2 = 0; qq2 < 16; qq2++) {
                    int k = qq2 * 32 + lane;
                    a = fmaf(xdc[half * 512 + k], __ldg(&hW[k * ODIM + wl]), a);
                }
#pragma unroll
                for (int d = 16; d; d >>= 1) a += __shfl_xor_sync(0xFFFFFFFFu, a, d);
                if (lane == 0) s_gv[half][wl] = a + __ldg(&hb[wl]);
            }
            __syncthreads();

            int lt = t & 511;
            bool is_out = ((i & 1) == 0);
            if (is_out) {
                if (lt < ODIM) out[b * (TSTEPS * ODIM) + i * ODIM + lt] = sigm(s_gv[bb][lt]);
                if (lt == 0) {
                    s_dv[bb][0] = (sigm(s_gv[bb][0]) > 0.5f) ? 1.0f : 0.0f;
                    s_dv[bb][1] = 1.0f; s_dv[bb][2] = 0.0f;
                }
            } else {
                if (lt == 0) {
                    float best = sigm(s_gv[bb][3]); int p = 0;
#pragma unroll
                    for (int c = 1; c < 6; c++) {
                        float v = sigm(s_gv[bb][3 + c]);
                        if (v > best) { best = v; p = c; }
                    }
                    s_ptr[bb] = p;
                    s_dv[bb][0] = 0.0f; s_dv[bb][1] = 0.0f; s_dv[bb][2] = 1.0f;
                }
                __syncthreads();               // uniform branch (step parity)
                ctx += __ldg(&g_enc[(b * 6 + s_ptr[bb]) * HSZ + h]);
                if (wl < ODIM) {
                    int eb = bid * 2 + half;
                    const float* ev = g_enc + (eb * 6 + s_ptr[half]) * HSZ;
                    float a2 = 0.0f;
#pragma unroll
                    for (int qq2 = 0; qq2 < 16; qq2++) {
                        int k = qq2 * 32 + lane;
                        a2 = fmaf(__ldg(&ev[k]), __ldg(&hW[k * ODIM + wl]), a2);
                    }
#pragma unroll
                    for (int d = 16; d; d >>= 1) a2 += __shfl_xor_sync(0xFFFFFFFFu, a2, d);
                    if (lane == 0)
                        out[(bid * 2 + half) * (TSTEPS * ODIM) + i * ODIM + wl] =
                            sigm(s_gv[half][wl] + a2);
                }
            }
            __syncthreads();

            if (i == TSTEPS - 1) break;

            // fused next-step S0 (dec is block-local in s_dv)
            float d0 = s_dv[bb][0], d1 = s_dv[bb][1], d2 = s_dv[bb][2];
            float x = fmaf(d0, __ldg(&inW[h]),
                      fmaf(d1, __ldg(&inW[HSZ + h]),
                      fmaf(d2, __ldg(&inW[2 * HSZ + h]), __ldg(&inb[h]))));
            float acc = 0.0f;
#pragma unroll
            for (int q4 = 0; q4 < 4; q4++) {
                float4 ca = __ldg((const float4*)(A + h * NSZ + q4 * 4));
                float4 cb4 = __ldg((const float4*)(Bm + h * NSZ + q4 * 4));
                float4 cc4 = __ldg((const float4*)(Cm + h * NSZ + q4 * 4));
                s0[q4 * 4 + 0] = fmaf(ca.x, s0[q4 * 4 + 0], cb4.x * x);
                s0[q4 * 4 + 1] = fmaf(ca.y, s0[q4 * 4 + 1], cb4.y * x);
                s0[q4 * 4 + 2] = fmaf(ca.z, s0[q4 * 4 + 2], cb4.z * x);
                s0[q4 * 4 + 3] = fmaf(ca.w, s0[q4 * 4 + 3], cb4.w * x);
                acc += cc4.x * s0[q4 * 4] + cc4.y * s0[q4 * 4 + 1]
                     + cc4.z * s0[q4 * 4 + 2] + cc4.w * s0[q4 * 4 + 3];
            }
            g_gact[b * HSZ + h] = gelu_exact(fmaf(__ldg(&D[h]), x, acc));
        }
        gbar(ep);
    }
}

// ============================================================
// Launch: 3 graph nodes
// ============================================================
extern "C" void kernel_launch(void* const* d_in, const int* in_sizes, int n_in,
                              void* d_out, int out_size) {
    int o = (n_in >= 14) ? 1 : 0;
    const float* inseq = (const float*)d_in[0];
    const float* inW = (const float*)d_in[1 + o];
    const float* inb = (const float*)d_in[2 + o];
    const float* A   = (const float*)d_in[3 + o];
    const float* Bm  = (const float*)d_in[4 + o];
    const float* Cm  = (const float*)d_in[5 + o];
    const float* D   = (const float*)d_in[6 + o];
    const float* oW  = (const float*)d_in[7 + o];
    const float* ob  = (const float*)d_in[8 + o];
    const float* lng = (const float*)d_in[9 + o];
    const float* lnb = (const float*)d_in[10 + o];
    const float* hW  = (const float*)d_in[11 + o];
    const float* hb  = (const float*)d_in[12 + o];
    float* out = (float*)d_out;

    cudaFuncSetAttribute(k_persist, cudaFuncAttributeMaxDynamicSharedMemorySize,
                         SMEM_BYTES);

    k_enc<<<(BSZ * 6 * HSZ) / 256, 256>>>(inseq, inW, inb);
    k_init<<<1, 32>>>();
    k_persist<<<NBLK, NTHR, SMEM_BYTES>>>(inW, inb, A, Bm, Cm, D,
                                          oW, ob, lng, lnb, hW, hb, out);
}